// round 7
// baseline (speedup 1.0000x reference)
#include <cuda_runtime.h>
#include <cuda_fp16.h>
#include <cstdint>

#define HID   1024
#define TS1   1001            // TYPE_SIZE + 1 embedding rows
#define MPAD  1024            // padded M (16 tiles of 64)
#define BATCH 32
#define SEQ   512
#define NTOK  (BATCH * SEQ)
#define NG    5               // used gates: gi, gz, go, gib, gd
#define NP    (NG * HID)      // 5120
#define WROW  2048            // W_rec row stride (2H)
#define KK    1024            // K (single-pass fp16)

// ---------------- device-global scratch (no allocs allowed) ----------------
__device__ __half g_A[MPAD * KK];            // 2 MB
__device__ __half g_B[NP * KK];              // 10 MB
__device__ int   g_off[TS1 + 1];             // token bucket offsets per event
__device__ int   g_pos[TS1];                 // running scatter cursors
__device__ int   g_tok[NTOK];                // (e<<16)|tok, sorted by e
__device__ float g_tdur[NTOK];               // durations aligned with g_tok

__constant__ int c_chunk[NG] = {0, 2, 3, 4, 6};   // gi, gz, go, gib, gd

// ---------------- base-target PTX helpers ----------------
__device__ __forceinline__ uint32_t smem_u32(const void* p) {
    uint32_t a;
    asm("{ .reg .u64 t; cvta.to.shared.u64 t, %1; cvt.u32.u64 %0, t; }"
        : "=r"(a) : "l"(p));
    return a;
}
#define CP_ASYNC16(dst, src) \
    asm volatile("cp.async.cg.shared.global [%0], [%1], 16;" \
                 :: "r"(dst), "l"(src))
#define CP_COMMIT() asm volatile("cp.async.commit_group;" ::: "memory")
#define CP_WAIT0()  asm volatile("cp.async.wait_group 0;" ::: "memory")
#define CP_WAIT1()  asm volatile("cp.async.wait_group 1;" ::: "memory")

__device__ __forceinline__ void ldsm_x4(uint32_t* r, uint32_t addr) {
    asm volatile("ldmatrix.sync.aligned.m8n8.x4.shared.b16 {%0,%1,%2,%3}, [%4];"
        : "=r"(r[0]), "=r"(r[1]), "=r"(r[2]), "=r"(r[3]) : "r"(addr));
}
__device__ __forceinline__ void mma_f16(float* c, const uint32_t* a,
                                        uint32_t b0, uint32_t b1) {
    asm volatile(
        "mma.sync.aligned.m16n8k16.row.col.f32.f16.f16.f32 "
        "{%0,%1,%2,%3}, {%4,%5,%6,%7}, {%8,%9}, {%0,%1,%2,%3};"
        : "+f"(c[0]), "+f"(c[1]), "+f"(c[2]), "+f"(c[3])
        : "r"(a[0]), "r"(a[1]), "r"(a[2]), "r"(a[3]), "r"(b0), "r"(b1));
}

// ---- fast transcendentals (MUFU) ----
#define LOG2E 1.4426950408889634f
#define LN2   0.6931471805599453f
__device__ __forceinline__ float ex2f(float x) {
    float y; asm("ex2.approx.f32 %0, %1;" : "=f"(y) : "f"(x)); return y;
}
__device__ __forceinline__ float lg2f(float x) {
    float y; asm("lg2.approx.f32 %0, %1;" : "=f"(y) : "f"(x)); return y;
}
__device__ __forceinline__ float rcpf(float x) {
    float y; asm("rcp.approx.f32 %0, %1;" : "=f"(y) : "f"(x)); return y;
}
__device__ __forceinline__ float fsigmoid(float x){ return rcpf(1.f + ex2f(-x * LOG2E)); }
__device__ __forceinline__ float fsoftplus(float x) {
    float e = ex2f(-fabsf(x) * LOG2E);
    return fmaxf(x, 0.f) + LN2 * lg2f(1.f + e);
}

// ---------------------------------------------------------------------------
// Conversion kernels
// ---------------------------------------------------------------------------
__global__ __launch_bounds__(256)
void conv_A(const float* __restrict__ emb) {
    int idx = blockIdx.x * 256 + threadIdx.x;
    if (idx >= MPAD * HID) return;
    int e = idx >> 10;
    float a = (e < TS1) ? emb[idx] : 0.f;
    g_A[idx] = __float2half_rn(a);
}

__global__ __launch_bounds__(256)
void conv_B(const float* __restrict__ W) {
    int idx = blockIdx.x * 256 + threadIdx.x;
    if (idx >= NP * HID) return;
    int n = idx >> 10, k = idx & 1023;
    int c = n >> 10, h = n & 1023;
    float a = W[(size_t)(c_chunk[c] * HID + h) * WROW + k];
    g_B[idx] = __float2half_rn(a);
}

// ---------------------------------------------------------------------------
// Token bucketing: zero -> histogram -> scan -> scatter
// ---------------------------------------------------------------------------
__global__ void k_zero() {
    int i = blockIdx.x * 1024 + threadIdx.x;
    if (i <= TS1) g_off[i] = 0;
}
__global__ __launch_bounds__(1024)
void k_hist(const int* __restrict__ ev) {
    int idx = blockIdx.x * 1024 + threadIdx.x;   // idx = b*SEQ + t
    if (idx < NTOK) atomicAdd(&g_off[ev[idx] + 1], 1);
}
__global__ __launch_bounds__(1024)
void k_scan() {
    __shared__ int sh[TS1 + 1];
    for (int i = threadIdx.x; i <= TS1; i += 1024) sh[i] = g_off[i];
    __syncthreads();
    if (threadIdx.x == 0) {
        int run = 0;
        for (int i = 0; i <= TS1; i++) { run += sh[i]; sh[i] = run; }
    }
    __syncthreads();
    for (int i = threadIdx.x; i <= TS1; i += 1024) g_off[i] = sh[i];
    for (int i = threadIdx.x; i < TS1; i += 1024) g_pos[i] = sh[i];
}
__global__ __launch_bounds__(1024)
void k_scatter(const int* __restrict__ ev, const float* __restrict__ dur) {
    int idx = blockIdx.x * 1024 + threadIdx.x;   // idx = b*SEQ + t
    if (idx >= NTOK) return;
    int e = ev[idx];
    int p = atomicAdd(&g_pos[e], 1);
    int b = idx / SEQ, t = idx - b * SEQ;
    g_tok[p]  = (e << 16) | (t * BATCH + b);     // tok matches output layout
    g_tdur[p] = dur[idx];
}

// ---------------------------------------------------------------------------
// FUSED kernel: 5-gate fp16 GEMM + activation -> SMEM tile -> token outputs.
// Block: 64 e-rows x 64 h-cols. Grid 16x16 = 256 blocks, single wave @2/SM.
// ---------------------------------------------------------------------------
#define BK      32
#define KT      (KK / BK)                 // 32
#define TILE_B  (64 * 80)                 // 5120 B per 64-row tile per stage
#define STG_B   (6 * TILE_B)              // 30720 B per stage
#define SMEM_SZ (3 * STG_B)               // 92160 B  (>= 4*64*66*4 = 67584)
#define TROW    66                        // padded smem-table row stride

__global__ __launch_bounds__(256, 2)
void gemm_fused(const float* __restrict__ brec, float* __restrict__ out) {
    extern __shared__ __align__(16) char smem[];
    const uint32_t sbase = smem_u32(smem);

    const int tid = threadIdx.x;
    const int wid = tid >> 5, lane = tid & 31;
    const int bh = blockIdx.x * 64;        // h-tile (within HID)
    const int bm = blockIdx.y * 64;        // e-tile
    const int wm = (wid >> 1) * 16;        // warp m offset: 0,16,32,48
    const int wn = (wid & 1) * 32;         // warp n offset: 0,32

    const __half* gA = g_A + (size_t)bm * KK;
    const __half* gB = g_B + (size_t)bh * KK;

    const int lrow = tid >> 2, lch = tid & 3;

    auto issue = [&](int kt, int s) {
        const int k0 = kt * BK;
        const uint32_t st = sbase + s * STG_B;
        const uint32_t doff = lrow * 80 + lch * 16;
        const size_t   soff = (size_t)lrow * KK + k0 + lch * 8;
        CP_ASYNC16(st + doff, gA + soff);
#pragma unroll
        for (int g = 0; g < NG; g++)
            CP_ASYNC16(st + (g + 1) * TILE_B + doff,
                       gB + (size_t)g * HID * KK + soff);
    };

    float acc[NG][4][4];
#pragma unroll
    for (int g = 0; g < NG; g++)
#pragma unroll
        for (int j = 0; j < 4; j++)
#pragma unroll
            for (int v = 0; v < 4; v++) acc[g][j][v] = 0.f;

    issue(0, 0); CP_COMMIT();
    issue(1, 1); CP_COMMIT();

    const uint32_t lmoff = (lane & 15) * 80 + (lane >> 4) * 16;

    int s = 0;
    for (int kt = 0; kt < KT; kt++) {
        if (kt < KT - 1) CP_WAIT1(); else CP_WAIT0();
        __syncthreads();

        const uint32_t aBase = sbase + s * STG_B;

#pragma unroll
        for (int ks = 0; ks < 2; ks++) {
            uint32_t af[4];
            ldsm_x4(af, aBase + wm * 80 + ks * 32 + lmoff);
            if (ks == 0 && kt + 2 < KT) {
                int s2 = s + 2; if (s2 >= 3) s2 -= 3;
                issue(kt + 2, s2);
                CP_COMMIT();
            }
#pragma unroll
            for (int g = 0; g < NG; g++) {
                const uint32_t bBase = aBase + (g + 1) * TILE_B + ks * 32 + lmoff;
                uint32_t b0[4], b1[4];
                ldsm_x4(b0, bBase + wn * 80);
                ldsm_x4(b1, bBase + (wn + 16) * 80);
                mma_f16(acc[g][0], af, b0[0], b0[2]);
                mma_f16(acc[g][1], af, b0[1], b0[3]);
                mma_f16(acc[g][2], af, b1[0], b1[2]);
                mma_f16(acc[g][3], af, b1[1], b1[3]);
            }
        }
        if (++s == 3) s = 0;
    }

    // ---- activation epilogue -> SMEM table tile (reuse pipeline smem) ----
    __syncthreads();                       // all warps past final ldsm reads
    float* tab = reinterpret_cast<float*>(smem);   // [4][64][TROW]

    const int cm = lane >> 2, cn = (lane & 3) * 2;
    const int le0 = wm + cm;               // local e rows le0, le0+8

#pragma unroll
    for (int nf = 0; nf < 4; nf++) {
        const int col = bh + wn + nf * 8 + cn;       // global h
        const int lc  = wn + nf * 8 + cn;            // local h
        const float2 bgi = *reinterpret_cast<const float2*>(brec + 0 * HID + col);
        const float2 bgz = *reinterpret_cast<const float2*>(brec + 2 * HID + col);
        const float2 bgo = *reinterpret_cast<const float2*>(brec + 3 * HID + col);
        const float2 bgb = *reinterpret_cast<const float2*>(brec + 4 * HID + col);
        const float2 bgd = *reinterpret_cast<const float2*>(brec + 6 * HID + col);
#pragma unroll
        for (int half = 0; half < 2; half++) {
            const int le = le0 + half * 8;
            const int v = half * 2;
            float gi0 = acc[0][nf][v] + bgi.x, gi1 = acc[0][nf][v + 1] + bgi.y;
            float gz0 = acc[1][nf][v] + bgz.x, gz1 = acc[1][nf][v + 1] + bgz.y;
            float go0 = acc[2][nf][v] + bgo.x, go1 = acc[2][nf][v + 1] + bgo.y;
            float gb0 = acc[3][nf][v] + bgb.x, gb1 = acc[3][nf][v + 1] + bgb.y;
            float gd0 = acc[4][nf][v] + bgd.x, gd1 = acc[4][nf][v + 1] + bgd.y;

            float tz0 = tanhf(gz0), tz1 = tanhf(gz1);
            float* T = tab + le * TROW + lc;
            *reinterpret_cast<float2*>(T + 0 * 64 * TROW) =
                make_float2(fsigmoid(gi0) * tz0, fsigmoid(gi1) * tz1);
            *reinterpret_cast<float2*>(T + 1 * 64 * TROW) =
                make_float2(fsigmoid(gb0) * tz0, fsigmoid(gb1) * tz1);
            *reinterpret_cast<float2*>(T + 2 * 64 * TROW) =
                make_float2(fsigmoid(go0), fsigmoid(go1));
            *reinterpret_cast<float2*>(T + 3 * 64 * TROW) =
                make_float2(fsoftplus(gd0), fsoftplus(gd1));
        }
    }
    __syncthreads();

    // ---- token phase: each warp takes every-8th token of this e-tile ----
    const int tEnd0 = bm + 64 < TS1 ? bm + 64 : TS1;
    const int start = g_off[bm];
    const int end   = g_off[tEnd0];
    const size_t stride = (size_t)SEQ * BATCH * HID;
    const int h2 = 2 * lane;               // local h pair handled by this lane

    for (int i = start + wid; i < end; i += 8) {
        const int   packed = g_tok[i];
        const float d      = g_tdur[i];
        const int   tok    = packed & 0xFFFF;
        const int   le     = (packed >> 16) - bm;
        const float dl     = -d * LOG2E;

        const float* T = tab + le * TROW + h2;
        float2 c  = *reinterpret_cast<const float2*>(T + 0 * 64 * TROW);
        float2 cb = *reinterpret_cast<const float2*>(T + 1 * 64 * TROW);
        float2 go = *reinterpret_cast<const float2*>(T + 2 * 64 * TROW);
        float2 gd = *reinterpret_cast<const float2*>(T + 3 * 64 * TROW);

        float2 hd;
        hd.x = go.x * tanhf(cb.x + (c.x - cb.x) * ex2f(gd.x * dl));
        hd.y = go.y * tanhf(cb.y + (c.y - cb.y) * ex2f(gd.y * dl));

        float* base = out + (size_t)tok * HID + bh + h2;
        __stcs(reinterpret_cast<float2*>(base + 0 * stride), hd);
        __stcs(reinterpret_cast<float2*>(base + 1 * stride), c);
        __stcs(reinterpret_cast<float2*>(base + 2 * stride), cb);
        __stcs(reinterpret_cast<float2*>(base + 3 * stride), go);
        __stcs(reinterpret_cast<float2*>(base + 4 * stride), gd);
    }
}

// ---------------------------------------------------------------------------
extern "C" void kernel_launch(void* const* d_in, const int* in_sizes, int n_in,
                              void* d_out, int out_size) {
    const int*   ev  = (const int*)  d_in[0];   // event_seqs   [32, 512] int32
    const float* dur = (const float*)d_in[1];   // duration_seqs[32, 512]
    const float* emb = (const float*)d_in[2];   // emb_table [1001, 1024]
    const float* W   = (const float*)d_in[3];   // W_rec [7168, 2048]
    const float* br  = (const float*)d_in[4];   // b_rec [7168]
    float* out = (float*)d_out;                 // [5, 512, 32, 1024]

    static bool attr_done = false;
    if (!attr_done) {
        cudaFuncSetAttribute(gemm_fused,
                             cudaFuncAttributeMaxDynamicSharedMemorySize,
                             SMEM_SZ);
        attr_done = true;
    }

    conv_A<<<(MPAD * HID + 255) / 256, 256>>>(emb);
    conv_B<<<(NP * HID + 255) / 256, 256>>>(W);

    k_zero<<<1, 1024>>>();
    k_hist<<<(NTOK + 1023) / 1024, 1024>>>(ev);
    k_scan<<<1, 1024>>>();
    k_scatter<<<(NTOK + 1023) / 1024, 1024>>>(ev, dur);

    dim3 g1(HID / 64, MPAD / 64);               // (16, 16) = 256 blocks
    gemm_fused<<<g1, 256, SMEM_SZ>>>(br, out);
}

// round 8
// speedup vs baseline: 1.2137x; 1.2137x over previous
#include <cuda_runtime.h>
#include <cuda_fp16.h>
#include <cstdint>

#define HID   1024
#define TS1   1001            // TYPE_SIZE + 1 embedding rows
#define MPAD  1024            // padded M (16 tiles of 64)
#define BATCH 32
#define SEQ   512
#define NTOK  (BATCH * SEQ)
#define NG    5               // used gates: gi, gz, go, gib, gd
#define NP    (NG * HID)      // 5120
#define WROW  2048            // W_rec row stride (2H)
#define KK    1024            // K (single-pass fp16)
#define ESPLIT 512            // e-range split point for overlap

// ---------------- device-global scratch (no allocs allowed) ----------------
__device__ __half g_A[MPAD * KK];            // 2 MB
__device__ __half g_B[NP * KK];              // 10 MB
__device__ float g_table[TS1 * 4 * HID];     // 16.4 MB {c, c_bar, sig(go), sp(gd)}
__device__ int   g_off[TS1 + 1];             // token bucket offsets per event
__device__ int   g_pos[TS1];                 // scatter cursors
__device__ int   g_tok[NTOK];                // (e<<16)|tok, bucketed by e
__device__ float g_tdur[NTOK];               // durations aligned with g_tok

__constant__ int c_chunk[NG] = {0, 2, 3, 4, 6};   // gi, gz, go, gib, gd

// ---------------- base-target PTX helpers ----------------
__device__ __forceinline__ uint32_t smem_u32(const void* p) {
    uint32_t a;
    asm("{ .reg .u64 t; cvta.to.shared.u64 t, %1; cvt.u32.u64 %0, t; }"
        : "=r"(a) : "l"(p));
    return a;
}
#define CP_ASYNC16(dst, src) \
    asm volatile("cp.async.cg.shared.global [%0], [%1], 16;" \
                 :: "r"(dst), "l"(src))
#define CP_COMMIT() asm volatile("cp.async.commit_group;" ::: "memory")
#define CP_WAIT0()  asm volatile("cp.async.wait_group 0;" ::: "memory")
#define CP_WAIT1()  asm volatile("cp.async.wait_group 1;" ::: "memory")

__device__ __forceinline__ void ldsm_x4(uint32_t* r, uint32_t addr) {
    asm volatile("ldmatrix.sync.aligned.m8n8.x4.shared.b16 {%0,%1,%2,%3}, [%4];"
        : "=r"(r[0]), "=r"(r[1]), "=r"(r[2]), "=r"(r[3]) : "r"(addr));
}
__device__ __forceinline__ void mma_f16(float* c, const uint32_t* a,
                                        uint32_t b0, uint32_t b1) {
    asm volatile(
        "mma.sync.aligned.m16n8k16.row.col.f32.f16.f16.f32 "
        "{%0,%1,%2,%3}, {%4,%5,%6,%7}, {%8,%9}, {%0,%1,%2,%3};"
        : "+f"(c[0]), "+f"(c[1]), "+f"(c[2]), "+f"(c[3])
        : "r"(a[0]), "r"(a[1]), "r"(a[2]), "r"(a[3]), "r"(b0), "r"(b1));
}

// ---- fast transcendentals (MUFU) ----
#define LOG2E 1.4426950408889634f
#define LN2   0.6931471805599453f
__device__ __forceinline__ float ex2f(float x) {
    float y; asm("ex2.approx.f32 %0, %1;" : "=f"(y) : "f"(x)); return y;
}
__device__ __forceinline__ float lg2f(float x) {
    float y; asm("lg2.approx.f32 %0, %1;" : "=f"(y) : "f"(x)); return y;
}
__device__ __forceinline__ float rcpf(float x) {
    float y; asm("rcp.approx.f32 %0, %1;" : "=f"(y) : "f"(x)); return y;
}
__device__ __forceinline__ float fsigmoid(float x){ return rcpf(1.f + ex2f(-x * LOG2E)); }
__device__ __forceinline__ float fsoftplus(float x) {
    float e = ex2f(-fabsf(x) * LOG2E);
    return fmaxf(x, 0.f) + LN2 * lg2f(1.f + e);
}

// ---------------------------------------------------------------------------
// Conversion kernels
// ---------------------------------------------------------------------------
__global__ __launch_bounds__(256)
void conv_A(const float* __restrict__ emb) {
    int idx = blockIdx.x * 256 + threadIdx.x;
    if (idx >= MPAD * HID) return;
    int e = idx >> 10;
    float a = (e < TS1) ? emb[idx] : 0.f;
    g_A[idx] = __float2half_rn(a);
}

__global__ __launch_bounds__(256)
void conv_B(const float* __restrict__ W) {
    int idx = blockIdx.x * 256 + threadIdx.x;
    if (idx >= NP * HID) return;
    int n = idx >> 10, k = idx & 1023;
    int c = n >> 10, h = n & 1023;
    float a = W[(size_t)(c_chunk[c] * HID + h) * WROW + k];
    g_B[idx] = __float2half_rn(a);
}

// ---------------------------------------------------------------------------
// Token bucketing: zero -> histogram -> scan -> scatter
// ---------------------------------------------------------------------------
__global__ void k_zero() {
    int i = blockIdx.x * 1024 + threadIdx.x;
    if (i <= TS1) g_off[i] = 0;
}
__global__ __launch_bounds__(1024)
void k_hist(const int* __restrict__ ev) {
    int idx = blockIdx.x * 1024 + threadIdx.x;   // idx = b*SEQ + t
    if (idx < NTOK) atomicAdd(&g_off[ev[idx] + 1], 1);
}
__global__ __launch_bounds__(1024)
void k_scan() {
    __shared__ int sh[TS1 + 1];
    for (int i = threadIdx.x; i <= TS1; i += 1024) sh[i] = g_off[i];
    __syncthreads();
    if (threadIdx.x == 0) {
        int run = 0;
        for (int i = 0; i <= TS1; i++) { run += sh[i]; sh[i] = run; }
    }
    __syncthreads();
    for (int i = threadIdx.x; i <= TS1; i += 1024) g_off[i] = sh[i];
    for (int i = threadIdx.x; i < TS1; i += 1024) g_pos[i] = sh[i];
}
__global__ __launch_bounds__(1024)
void k_scatter(const int* __restrict__ ev, const float* __restrict__ dur) {
    int idx = blockIdx.x * 1024 + threadIdx.x;   // idx = b*SEQ + t
    if (idx >= NTOK) return;
    int e = ev[idx];
    int p = atomicAdd(&g_pos[e], 1);
    int b = idx / SEQ, t = idx - b * SEQ;
    g_tok[p]  = (e << 16) | (t * BATCH + b);     // tok matches output layout
    g_tdur[p] = dur[idx];
}

// ---------------------------------------------------------------------------
// GEMM half: 5-gate fp16 GEMM + activation epilogue -> g_table.
// Covers e rows [bm_base, bm_base+512). Grid (16, 8) = 128 blocks (solo wave).
// ---------------------------------------------------------------------------
#define BK      32
#define KT      (KK / BK)                 // 32
#define TILE_B  (64 * 80)                 // 5120 B per 64-row tile per stage
#define STG_B   (6 * TILE_B)              // 30720 B per stage
#define SMEM_SZ (3 * STG_B)               // 92160 B

__global__ __launch_bounds__(256, 2)
void gemm_half(const float* __restrict__ brec, int bm_base) {
    extern __shared__ __align__(16) char smem[];
    const uint32_t sbase = smem_u32(smem);

    const int tid = threadIdx.x;
    const int wid = tid >> 5, lane = tid & 31;
    const int bh = blockIdx.x * 64;        // h-tile (within HID)
    const int bm = bm_base + blockIdx.y * 64;   // e-tile
    const int wm = (wid >> 1) * 16;        // warp m offset: 0,16,32,48
    const int wn = (wid & 1) * 32;         // warp n offset: 0,32

    const __half* gA = g_A + (size_t)bm * KK;
    const __half* gB = g_B + (size_t)bh * KK;

    const int lrow = tid >> 2, lch = tid & 3;

    auto issue = [&](int kt, int s) {
        const int k0 = kt * BK;
        const uint32_t st = sbase + s * STG_B;
        const uint32_t doff = lrow * 80 + lch * 16;
        const size_t   soff = (size_t)lrow * KK + k0 + lch * 8;
        CP_ASYNC16(st + doff, gA + soff);
#pragma unroll
        for (int g = 0; g < NG; g++)
            CP_ASYNC16(st + (g + 1) * TILE_B + doff,
                       gB + (size_t)g * HID * KK + soff);
    };

    float acc[NG][4][4];
#pragma unroll
    for (int g = 0; g < NG; g++)
#pragma unroll
        for (int j = 0; j < 4; j++)
#pragma unroll
            for (int v = 0; v < 4; v++) acc[g][j][v] = 0.f;

    issue(0, 0); CP_COMMIT();
    issue(1, 1); CP_COMMIT();

    const uint32_t lmoff = (lane & 15) * 80 + (lane >> 4) * 16;

    int s = 0;
    for (int kt = 0; kt < KT; kt++) {
        if (kt < KT - 1) CP_WAIT1(); else CP_WAIT0();
        __syncthreads();

        const uint32_t aBase = sbase + s * STG_B;

#pragma unroll
        for (int ks = 0; ks < 2; ks++) {
            uint32_t af[4];
            ldsm_x4(af, aBase + wm * 80 + ks * 32 + lmoff);
            if (ks == 0 && kt + 2 < KT) {
                int s2 = s + 2; if (s2 >= 3) s2 -= 3;
                issue(kt + 2, s2);
                CP_COMMIT();
            }
#pragma unroll
            for (int g = 0; g < NG; g++) {
                const uint32_t bBase = aBase + (g + 1) * TILE_B + ks * 32 + lmoff;
                uint32_t b0[4], b1[4];
                ldsm_x4(b0, bBase + wn * 80);
                ldsm_x4(b1, bBase + (wn + 16) * 80);
                mma_f16(acc[g][0], af, b0[0], b0[2]);
                mma_f16(acc[g][1], af, b0[1], b0[3]);
                mma_f16(acc[g][2], af, b1[0], b1[2]);
                mma_f16(acc[g][3], af, b1[1], b1[3]);
            }
        }
        if (++s == 3) s = 0;
    }

    // ---- fused activation epilogue -> g_table ----
    const int cm = lane >> 2, cn = (lane & 3) * 2;
    const int e0 = bm + wm + cm;
    const int e1 = e0 + 8;

#pragma unroll
    for (int nf = 0; nf < 4; nf++) {
        const int col = bh + wn + nf * 8 + cn;
        const float2 bgi = *reinterpret_cast<const float2*>(brec + 0 * HID + col);
        const float2 bgz = *reinterpret_cast<const float2*>(brec + 2 * HID + col);
        const float2 bgo = *reinterpret_cast<const float2*>(brec + 3 * HID + col);
        const float2 bgb = *reinterpret_cast<const float2*>(brec + 4 * HID + col);
        const float2 bgd = *reinterpret_cast<const float2*>(brec + 6 * HID + col);
#pragma unroll
        for (int half = 0; half < 2; half++) {
            const int e = half ? e1 : e0;
            if (e >= TS1) continue;
            const int v = half * 2;
            float gi0 = acc[0][nf][v] + bgi.x, gi1 = acc[0][nf][v + 1] + bgi.y;
            float gz0 = acc[1][nf][v] + bgz.x, gz1 = acc[1][nf][v + 1] + bgz.y;
            float go0 = acc[2][nf][v] + bgo.x, go1 = acc[2][nf][v + 1] + bgo.y;
            float gb0 = acc[3][nf][v] + bgb.x, gb1 = acc[3][nf][v + 1] + bgb.y;
            float gd0 = acc[4][nf][v] + bgd.x, gd1 = acc[4][nf][v + 1] + bgd.y;

            float tz0 = tanhf(gz0), tz1 = tanhf(gz1);
            float* T = g_table + (size_t)e * (4 * HID) + col;
            *reinterpret_cast<float2*>(T + 0 * HID) =
                make_float2(fsigmoid(gi0) * tz0, fsigmoid(gi1) * tz1);
            *reinterpret_cast<float2*>(T + 1 * HID) =
                make_float2(fsigmoid(gb0) * tz0, fsigmoid(gb1) * tz1);
            *reinterpret_cast<float2*>(T + 2 * HID) =
                make_float2(fsigmoid(go0), fsigmoid(go1));
            *reinterpret_cast<float2*>(T + 3 * HID) =
                make_float2(fsoftplus(gd0), fsoftplus(gd1));
        }
    }
}

// ---------------------------------------------------------------------------
// Token kernel over a bucket range [g_off[elo], g_off[ehi]).
// One block per bucketed token; grid oversized with early exit.
// ---------------------------------------------------------------------------
#define TOK_GRID 12288

__global__ __launch_bounds__(256)
void token_b(float* __restrict__ out, int elo, int ehi) {
    const int idx = g_off[elo] + blockIdx.x;
    if (idx >= g_off[ehi]) return;

    const int   packed = g_tok[idx];
    const float d      = g_tdur[idx];
    const int   tok    = packed & 0xFFFF;
    const int   e      = packed >> 16;
    const float dl     = -d * LOG2E;

    const float* T = g_table + (size_t)e * (4 * HID);
    const int h = threadIdx.x * 4;

    float4 c  = *reinterpret_cast<const float4*>(T + 0 * HID + h);
    float4 cb = *reinterpret_cast<const float4*>(T + 1 * HID + h);
    float4 go = *reinterpret_cast<const float4*>(T + 2 * HID + h);
    float4 gd = *reinterpret_cast<const float4*>(T + 3 * HID + h);

    float4 hd;
    hd.x = go.x * tanhf(cb.x + (c.x - cb.x) * ex2f(gd.x * dl));
    hd.y = go.y * tanhf(cb.y + (c.y - cb.y) * ex2f(gd.y * dl));
    hd.z = go.z * tanhf(cb.z + (c.z - cb.z) * ex2f(gd.z * dl));
    hd.w = go.w * tanhf(cb.w + (c.w - cb.w) * ex2f(gd.w * dl));

    const size_t stride = (size_t)SEQ * BATCH * HID;
    float* base = out + (size_t)tok * HID + h;

    __stcs(reinterpret_cast<float4*>(base + 0 * stride), hd);
    __stcs(reinterpret_cast<float4*>(base + 1 * stride), c);
    __stcs(reinterpret_cast<float4*>(base + 2 * stride), cb);
    __stcs(reinterpret_cast<float4*>(base + 3 * stride), go);
    __stcs(reinterpret_cast<float4*>(base + 4 * stride), gd);
}

// ---------------------------------------------------------------------------
extern "C" void kernel_launch(void* const* d_in, const int* in_sizes, int n_in,
                              void* d_out, int out_size) {
    const int*   ev  = (const int*)  d_in[0];   // event_seqs   [32, 512] int32
    const float* dur = (const float*)d_in[1];   // duration_seqs[32, 512]
    const float* emb = (const float*)d_in[2];   // emb_table [1001, 1024]
    const float* W   = (const float*)d_in[3];   // W_rec [7168, 2048]
    const float* br  = (const float*)d_in[4];   // b_rec [7168]
    float* out = (float*)d_out;                 // [5, 512, 32, 1024]

    static cudaStream_t s2;
    static cudaEvent_t evFork, evG0, evG1, evEnd;
    static bool init_done = false;
    if (!init_done) {
        cudaFuncSetAttribute(gemm_half,
                             cudaFuncAttributeMaxDynamicSharedMemorySize,
                             SMEM_SZ);
        cudaStreamCreateWithFlags(&s2, cudaStreamNonBlocking);
        cudaEventCreateWithFlags(&evFork, cudaEventDisableTiming);
        cudaEventCreateWithFlags(&evG0,   cudaEventDisableTiming);
        cudaEventCreateWithFlags(&evG1,   cudaEventDisableTiming);
        cudaEventCreateWithFlags(&evEnd,  cudaEventDisableTiming);
        init_done = true;
    }

    // fork side stream for bucketing (independent of convs/gemm)
    cudaEventRecord(evFork, 0);
    cudaStreamWaitEvent(s2, evFork, 0);
    k_zero<<<1, 1024, 0, s2>>>();
    k_hist<<<(NTOK + 1023) / 1024, 1024, 0, s2>>>(ev);
    k_scan<<<1, 1024, 0, s2>>>();
    k_scatter<<<(NTOK + 1023) / 1024, 1024, 0, s2>>>(ev, dur);

    // main stream: conversions, then gemm halves
    conv_A<<<(MPAD * HID + 255) / 256, 256>>>(emb);
    conv_B<<<(NP * HID + 255) / 256, 256>>>(W);

    dim3 gh(HID / 64, ESPLIT / 64);             // (16, 8) = 128 blocks
    gemm_half<<<gh, 256, SMEM_SZ>>>(br, 0);     // e 0..511
    cudaEventRecord(evG0, 0);
    gemm_half<<<gh, 256, SMEM_SZ>>>(br, ESPLIT);// e 512..1023
    cudaEventRecord(evG1, 0);

    // side stream: token half 0 overlaps gemm half 1
    cudaStreamWaitEvent(s2, evG0, 0);
    token_b<<<TOK_GRID, 256, 0, s2>>>(out, 0, ESPLIT);

    // side stream: token half 1 after gemm half 1 (overlaps token half 0 tail)
    cudaStreamWaitEvent(s2, evG1, 0);
    token_b<<<TOK_GRID, 256, 0, s2>>>(out, ESPLIT, TS1);

    // join side stream back into the captured origin stream
    cudaEventRecord(evEnd, s2);
    cudaStreamWaitEvent(0, evEnd, 0);
}

// round 9
// speedup vs baseline: 1.2165x; 1.0023x over previous
#include <cuda_runtime.h>
#include <cuda_fp16.h>
#include <cstdint>

#define HID   1024
#define TS1   1001            // TYPE_SIZE + 1 embedding rows
#define MPAD  1024            // padded M (16 tiles of 64)
#define BATCH 32
#define SEQ   512
#define NTOK  (BATCH * SEQ)
#define NG    5               // used gates: gi, gz, go, gib, gd
#define NP    (NG * HID)      // 5120
#define WROW  2048            // W_rec row stride (2H)
#define KK    1024            // K (single-pass fp16)
#define ESPLIT 512            // e-range split point for overlap

// ---------------- device-global scratch (no allocs allowed) ----------------
__device__ __half g_A[MPAD * KK];            // 2 MB
__device__ __half g_B[NP * KK];              // 10 MB
__device__ float g_table[TS1 * 4 * HID];     // 16.4 MB {c, c_bar, sig(go), sp(gd)}
__device__ int   g_off[TS1 + 1];             // token bucket offsets per event
__device__ int   g_pos[TS1];                 // scatter cursors
__device__ int   g_tok[NTOK];                // (e<<16)|tok, bucketed by e
__device__ float g_tdur[NTOK];               // durations aligned with g_tok

__constant__ int c_chunk[NG] = {0, 2, 3, 4, 6};   // gi, gz, go, gib, gd

// ---------------- base-target PTX helpers ----------------
__device__ __forceinline__ uint32_t smem_u32(const void* p) {
    uint32_t a;
    asm("{ .reg .u64 t; cvta.to.shared.u64 t, %1; cvt.u32.u64 %0, t; }"
        : "=r"(a) : "l"(p));
    return a;
}
#define CP_ASYNC16(dst, src) \
    asm volatile("cp.async.cg.shared.global [%0], [%1], 16;" \
                 :: "r"(dst), "l"(src))
#define CP_COMMIT() asm volatile("cp.async.commit_group;" ::: "memory")
#define CP_WAIT0()  asm volatile("cp.async.wait_group 0;" ::: "memory")
#define CP_WAIT1()  asm volatile("cp.async.wait_group 1;" ::: "memory")

__device__ __forceinline__ void ldsm_x4(uint32_t* r, uint32_t addr) {
    asm volatile("ldmatrix.sync.aligned.m8n8.x4.shared.b16 {%0,%1,%2,%3}, [%4];"
        : "=r"(r[0]), "=r"(r[1]), "=r"(r[2]), "=r"(r[3]) : "r"(addr));
}
__device__ __forceinline__ void mma_f16(float* c, const uint32_t* a,
                                        uint32_t b0, uint32_t b1) {
    asm volatile(
        "mma.sync.aligned.m16n8k16.row.col.f32.f16.f16.f32 "
        "{%0,%1,%2,%3}, {%4,%5,%6,%7}, {%8,%9}, {%0,%1,%2,%3};"
        : "+f"(c[0]), "+f"(c[1]), "+f"(c[2]), "+f"(c[3])
        : "r"(a[0]), "r"(a[1]), "r"(a[2]), "r"(a[3]), "r"(b0), "r"(b1));
}

// ---- fast transcendentals (MUFU) ----
#define LOG2E 1.4426950408889634f
#define LN2   0.6931471805599453f
__device__ __forceinline__ float ex2f(float x) {
    float y; asm("ex2.approx.f32 %0, %1;" : "=f"(y) : "f"(x)); return y;
}
__device__ __forceinline__ float lg2f(float x) {
    float y; asm("lg2.approx.f32 %0, %1;" : "=f"(y) : "f"(x)); return y;
}
__device__ __forceinline__ float rcpf(float x) {
    float y; asm("rcp.approx.f32 %0, %1;" : "=f"(y) : "f"(x)); return y;
}
__device__ __forceinline__ float fsigmoid(float x){ return rcpf(1.f + ex2f(-x * LOG2E)); }
__device__ __forceinline__ float fsoftplus(float x) {
    float e = ex2f(-fabsf(x) * LOG2E);
    return fmaxf(x, 0.f) + LN2 * lg2f(1.f + e);
}

// ---------------------------------------------------------------------------
// Conversion kernels
// ---------------------------------------------------------------------------
__global__ __launch_bounds__(256)
void conv_A(const float* __restrict__ emb) {
    int idx = blockIdx.x * 256 + threadIdx.x;
    if (idx >= MPAD * HID) return;
    int e = idx >> 10;
    float a = (e < TS1) ? emb[idx] : 0.f;
    g_A[idx] = __float2half_rn(a);
}

__global__ __launch_bounds__(256)
void conv_B(const float* __restrict__ W) {
    int idx = blockIdx.x * 256 + threadIdx.x;
    if (idx >= NP * HID) return;
    int n = idx >> 10, k = idx & 1023;
    int c = n >> 10, h = n & 1023;
    float a = W[(size_t)(c_chunk[c] * HID + h) * WROW + k];
    g_B[idx] = __float2half_rn(a);
}

// ---------------------------------------------------------------------------
// Token bucketing: zero -> histogram -> scan -> scatter
// ---------------------------------------------------------------------------
__global__ void k_zero() {
    int i = blockIdx.x * 1024 + threadIdx.x;
    if (i <= TS1) g_off[i] = 0;
}
__global__ __launch_bounds__(1024)
void k_hist(const int* __restrict__ ev) {
    int idx = blockIdx.x * 1024 + threadIdx.x;   // idx = b*SEQ + t
    if (idx < NTOK) atomicAdd(&g_off[ev[idx] + 1], 1);
}
__global__ __launch_bounds__(1024)
void k_scan() {
    __shared__ int sh[TS1 + 1];
    for (int i = threadIdx.x; i <= TS1; i += 1024) sh[i] = g_off[i];
    __syncthreads();
    if (threadIdx.x == 0) {
        int run = 0;
        for (int i = 0; i <= TS1; i++) { run += sh[i]; sh[i] = run; }
    }
    __syncthreads();
    for (int i = threadIdx.x; i <= TS1; i += 1024) g_off[i] = sh[i];
    for (int i = threadIdx.x; i < TS1; i += 1024) g_pos[i] = sh[i];
}
__global__ __launch_bounds__(1024)
void k_scatter(const int* __restrict__ ev, const float* __restrict__ dur) {
    int idx = blockIdx.x * 1024 + threadIdx.x;   // idx = b*SEQ + t
    if (idx >= NTOK) return;
    int e = ev[idx];
    int p = atomicAdd(&g_pos[e], 1);
    int b = idx / SEQ, t = idx - b * SEQ;
    g_tok[p]  = (e << 16) | (t * BATCH + b);     // tok matches output layout
    g_tdur[p] = dur[idx];
}

// ---------------------------------------------------------------------------
// GEMM half: 5-gate fp16 GEMM + activation epilogue -> g_table.
// Covers e rows [bm_base, bm_base+512). Grid (16, 8) = 128 blocks.
// ---------------------------------------------------------------------------
#define BK      32
#define KT      (KK / BK)                 // 32
#define TILE_B  (64 * 80)                 // 5120 B per 64-row tile per stage
#define STG_B   (6 * TILE_B)              // 30720 B per stage
#define SMEM_SZ (3 * STG_B)               // 92160 B

__global__ __launch_bounds__(256, 2)
void gemm_half(const float* __restrict__ brec, int bm_base) {
    extern __shared__ __align__(16) char smem[];
    const uint32_t sbase = smem_u32(smem);

    const int tid = threadIdx.x;
    const int wid = tid >> 5, lane = tid & 31;
    const int bh = blockIdx.x * 64;        // h-tile (within HID)
    const int bm = bm_base + blockIdx.y * 64;   // e-tile
    const int wm = (wid >> 1) * 16;        // warp m offset: 0,16,32,48
    const int wn = (wid & 1) * 32;         // warp n offset: 0,32

    const __half* gA = g_A + (size_t)bm * KK;
    const __half* gB = g_B + (size_t)bh * KK;

    const int lrow = tid >> 2, lch = tid & 3;

    auto issue = [&](int kt, int s) {
        const int k0 = kt * BK;
        const uint32_t st = sbase + s * STG_B;
        const uint32_t doff = lrow * 80 + lch * 16;
        const size_t   soff = (size_t)lrow * KK + k0 + lch * 8;
        CP_ASYNC16(st + doff, gA + soff);
#pragma unroll
        for (int g = 0; g < NG; g++)
            CP_ASYNC16(st + (g + 1) * TILE_B + doff,
                       gB + (size_t)g * HID * KK + soff);
    };

    float acc[NG][4][4];
#pragma unroll
    for (int g = 0; g < NG; g++)
#pragma unroll
        for (int j = 0; j < 4; j++)
#pragma unroll
            for (int v = 0; v < 4; v++) acc[g][j][v] = 0.f;

    issue(0, 0); CP_COMMIT();
    issue(1, 1); CP_COMMIT();

    const uint32_t lmoff = (lane & 15) * 80 + (lane >> 4) * 16;

    int s = 0;
    for (int kt = 0; kt < KT; kt++) {
        if (kt < KT - 1) CP_WAIT1(); else CP_WAIT0();
        __syncthreads();

        const uint32_t aBase = sbase + s * STG_B;

#pragma unroll
        for (int ks = 0; ks < 2; ks++) {
            uint32_t af[4];
            ldsm_x4(af, aBase + wm * 80 + ks * 32 + lmoff);
            if (ks == 0 && kt + 2 < KT) {
                int s2 = s + 2; if (s2 >= 3) s2 -= 3;
                issue(kt + 2, s2);
                CP_COMMIT();
            }
#pragma unroll
            for (int g = 0; g < NG; g++) {
                const uint32_t bBase = aBase + (g + 1) * TILE_B + ks * 32 + lmoff;
                uint32_t b0[4], b1[4];
                ldsm_x4(b0, bBase + wn * 80);
                ldsm_x4(b1, bBase + (wn + 16) * 80);
                mma_f16(acc[g][0], af, b0[0], b0[2]);
                mma_f16(acc[g][1], af, b0[1], b0[3]);
                mma_f16(acc[g][2], af, b1[0], b1[2]);
                mma_f16(acc[g][3], af, b1[1], b1[3]);
            }
        }
        if (++s == 3) s = 0;
    }

    // ---- fused activation epilogue -> g_table ----
    const int cm = lane >> 2, cn = (lane & 3) * 2;
    const int e0 = bm + wm + cm;
    const int e1 = e0 + 8;

#pragma unroll
    for (int nf = 0; nf < 4; nf++) {
        const int col = bh + wn + nf * 8 + cn;
        const float2 bgi = *reinterpret_cast<const float2*>(brec + 0 * HID + col);
        const float2 bgz = *reinterpret_cast<const float2*>(brec + 2 * HID + col);
        const float2 bgo = *reinterpret_cast<const float2*>(brec + 3 * HID + col);
        const float2 bgb = *reinterpret_cast<const float2*>(brec + 4 * HID + col);
        const float2 bgd = *reinterpret_cast<const float2*>(brec + 6 * HID + col);
#pragma unroll
        for (int half = 0; half < 2; half++) {
            const int e = half ? e1 : e0;
            if (e >= TS1) continue;
            const int v = half * 2;
            float gi0 = acc[0][nf][v] + bgi.x, gi1 = acc[0][nf][v + 1] + bgi.y;
            float gz0 = acc[1][nf][v] + bgz.x, gz1 = acc[1][nf][v + 1] + bgz.y;
            float go0 = acc[2][nf][v] + bgo.x, go1 = acc[2][nf][v + 1] + bgo.y;
            float gb0 = acc[3][nf][v] + bgb.x, gb1 = acc[3][nf][v + 1] + bgb.y;
            float gd0 = acc[4][nf][v] + bgd.x, gd1 = acc[4][nf][v + 1] + bgd.y;

            float tz0 = tanhf(gz0), tz1 = tanhf(gz1);
            float* T = g_table + (size_t)e * (4 * HID) + col;
            *reinterpret_cast<float2*>(T + 0 * HID) =
                make_float2(fsigmoid(gi0) * tz0, fsigmoid(gi1) * tz1);
            *reinterpret_cast<float2*>(T + 1 * HID) =
                make_float2(fsigmoid(gb0) * tz0, fsigmoid(gb1) * tz1);
            *reinterpret_cast<float2*>(T + 2 * HID) =
                make_float2(fsigmoid(go0), fsigmoid(go1));
            *reinterpret_cast<float2*>(T + 3 * HID) =
                make_float2(fsoftplus(gd0), fsoftplus(gd1));
        }
    }
}

// ---------------------------------------------------------------------------
// Token kernel over a bucket range [g_off[elo], g_off[ehi]).
// ---------------------------------------------------------------------------
#define TOK_GRID 12288

__global__ __launch_bounds__(256)
void token_b(float* __restrict__ out, int elo, int ehi) {
    const int idx = g_off[elo] + blockIdx.x;
    if (idx >= g_off[ehi]) return;

    const int   packed = g_tok[idx];
    const float d      = g_tdur[idx];
    const int   tok    = packed & 0xFFFF;
    const int   e      = packed >> 16;
    const float dl     = -d * LOG2E;

    const float* T = g_table + (size_t)e * (4 * HID);
    const int h = threadIdx.x * 4;

    float4 c  = *reinterpret_cast<const float4*>(T + 0 * HID + h);
    float4 cb = *reinterpret_cast<const float4*>(T + 1 * HID + h);
    float4 go = *reinterpret_cast<const float4*>(T + 2 * HID + h);
    float4 gd = *reinterpret_cast<const float4*>(T + 3 * HID + h);

    float4 hd;
    hd.x = go.x * tanhf(cb.x + (c.x - cb.x) * ex2f(gd.x * dl));
    hd.y = go.y * tanhf(cb.y + (c.y - cb.y) * ex2f(gd.y * dl));
    hd.z = go.z * tanhf(cb.z + (c.z - cb.z) * ex2f(gd.z * dl));
    hd.w = go.w * tanhf(cb.w + (c.w - cb.w) * ex2f(gd.w * dl));

    const size_t stride = (size_t)SEQ * BATCH * HID;
    float* base = out + (size_t)tok * HID + h;

    __stcs(reinterpret_cast<float4*>(base + 0 * stride), hd);
    __stcs(reinterpret_cast<float4*>(base + 1 * stride), c);
    __stcs(reinterpret_cast<float4*>(base + 2 * stride), cb);
    __stcs(reinterpret_cast<float4*>(base + 3 * stride), go);
    __stcs(reinterpret_cast<float4*>(base + 4 * stride), gd);
}

// ---------------------------------------------------------------------------
extern "C" void kernel_launch(void* const* d_in, const int* in_sizes, int n_in,
                              void* d_out, int out_size) {
    const int*   ev  = (const int*)  d_in[0];   // event_seqs   [32, 512] int32
    const float* dur = (const float*)d_in[1];   // duration_seqs[32, 512]
    const float* emb = (const float*)d_in[2];   // emb_table [1001, 1024]
    const float* W   = (const float*)d_in[3];   // W_rec [7168, 2048]
    const float* br  = (const float*)d_in[4];   // b_rec [7168]
    float* out = (float*)d_out;                 // [5, 512, 32, 1024]

    static cudaStream_t s1, s2;                 // both NON-BLOCKING: no legacy
    static cudaEvent_t evFork, evG0, evG1, evJ1, evJ2;
    static bool init_done = false;
    if (!init_done) {
        cudaFuncSetAttribute(gemm_half,
                             cudaFuncAttributeMaxDynamicSharedMemorySize,
                             SMEM_SZ);
        cudaStreamCreateWithFlags(&s1, cudaStreamNonBlocking);
        cudaStreamCreateWithFlags(&s2, cudaStreamNonBlocking);
        cudaEventCreateWithFlags(&evFork, cudaEventDisableTiming);
        cudaEventCreateWithFlags(&evG0,   cudaEventDisableTiming);
        cudaEventCreateWithFlags(&evG1,   cudaEventDisableTiming);
        cudaEventCreateWithFlags(&evJ1,   cudaEventDisableTiming);
        cudaEventCreateWithFlags(&evJ2,   cudaEventDisableTiming);
        init_done = true;
    }

    // ---- fork: stream 0 touched ONCE here ----
    cudaEventRecord(evFork, 0);
    cudaStreamWaitEvent(s1, evFork, 0);
    cudaStreamWaitEvent(s2, evFork, 0);

    // ---- s1: conversions + gemm halves (compute branch) ----
    conv_A<<<(MPAD * HID + 255) / 256, 256, 0, s1>>>(emb);
    conv_B<<<(NP * HID + 255) / 256, 256, 0, s1>>>(W);
    dim3 gh(HID / 64, ESPLIT / 64);             // (16, 8) = 128 blocks
    gemm_half<<<gh, 256, SMEM_SZ, s1>>>(br, 0);       // e 0..511
    cudaEventRecord(evG0, s1);
    gemm_half<<<gh, 256, SMEM_SZ, s1>>>(br, ESPLIT);  // e 512..1023
    cudaEventRecord(evG1, s1);

    // ---- s2: bucketing (parallel with conv+gemm0), then token halves ----
    k_zero<<<1, 1024, 0, s2>>>();
    k_hist<<<(NTOK + 1023) / 1024, 1024, 0, s2>>>(ev);
    k_scan<<<1, 1024, 0, s2>>>();
    k_scatter<<<(NTOK + 1023) / 1024, 1024, 0, s2>>>(ev, dur);

    cudaStreamWaitEvent(s2, evG0, 0);
    token_b<<<TOK_GRID, 256, 0, s2>>>(out, 0, ESPLIT);      // overlaps gemm1
    cudaStreamWaitEvent(s2, evG1, 0);
    token_b<<<TOK_GRID, 256, 0, s2>>>(out, ESPLIT, TS1);

    // ---- join both branches back into the origin stream ----
    cudaEventRecord(evJ1, s1);
    cudaEventRecord(evJ2, s2);
    cudaStreamWaitEvent(0, evJ1, 0);
    cudaStreamWaitEvent(0, evJ2, 0);
}

// round 10
// speedup vs baseline: 1.2346x; 1.0148x over previous
#include <cuda_runtime.h>
#include <cuda_fp16.h>
#include <cstdint>

#define HID   1024
#define TS1   1001            // TYPE_SIZE + 1 embedding rows
#define MPAD  1024            // padded M (16 tiles of 64)
#define BATCH 32
#define SEQ   512
#define NTOK  (BATCH * SEQ)
#define NG    5               // used gates: gi, gz, go, gib, gd
#define NP    (NG * HID)      // 5120
#define WROW  2048            // W_rec row stride (2H)
#define KK    1024            // K (single-pass fp16)
#define ESPLIT 512            // e-range split point

// ---------------- device-global scratch (no allocs allowed) ----------------
__device__ __half g_A[MPAD * KK];            // 2 MB
__device__ __half g_B[NP * KK];              // 10 MB
__device__ float g_table[TS1 * 4 * HID];     // 16.4 MB {c, c_bar, sig(go), sp(gd)}

__constant__ int c_chunk[NG] = {0, 2, 3, 4, 6};   // gi, gz, go, gib, gd

// ---------------- base-target PTX helpers ----------------
__device__ __forceinline__ uint32_t smem_u32(const void* p) {
    uint32_t a;
    asm("{ .reg .u64 t; cvta.to.shared.u64 t, %1; cvt.u32.u64 %0, t; }"
        : "=r"(a) : "l"(p));
    return a;
}
#define CP_ASYNC16(dst, src) \
    asm volatile("cp.async.cg.shared.global [%0], [%1], 16;" \
                 :: "r"(dst), "l"(src))
#define CP_COMMIT() asm volatile("cp.async.commit_group;" ::: "memory")
#define CP_WAIT0()  asm volatile("cp.async.wait_group 0;" ::: "memory")
#define CP_WAIT1()  asm volatile("cp.async.wait_group 1;" ::: "memory")

__device__ __forceinline__ void ldsm_x4(uint32_t* r, uint32_t addr) {
    asm volatile("ldmatrix.sync.aligned.m8n8.x4.shared.b16 {%0,%1,%2,%3}, [%4];"
        : "=r"(r[0]), "=r"(r[1]), "=r"(r[2]), "=r"(r[3]) : "r"(addr));
}
__device__ __forceinline__ void mma_f16(float* c, const uint32_t* a,
                                        uint32_t b0, uint32_t b1) {
    asm volatile(
        "mma.sync.aligned.m16n8k16.row.col.f32.f16.f16.f32 "
        "{%0,%1,%2,%3}, {%4,%5,%6,%7}, {%8,%9}, {%0,%1,%2,%3};"
        : "+f"(c[0]), "+f"(c[1]), "+f"(c[2]), "+f"(c[3])
        : "r"(a[0]), "r"(a[1]), "r"(a[2]), "r"(a[3]), "r"(b0), "r"(b1));
}

// ---- fast transcendentals (MUFU) ----
#define LOG2E 1.4426950408889634f
#define LN2   0.6931471805599453f
__device__ __forceinline__ float ex2f(float x) {
    float y; asm("ex2.approx.f32 %0, %1;" : "=f"(y) : "f"(x)); return y;
}
__device__ __forceinline__ float lg2f(float x) {
    float y; asm("lg2.approx.f32 %0, %1;" : "=f"(y) : "f"(x)); return y;
}
__device__ __forceinline__ float rcpf(float x) {
    float y; asm("rcp.approx.f32 %0, %1;" : "=f"(y) : "f"(x)); return y;
}
__device__ __forceinline__ float fsigmoid(float x){ return rcpf(1.f + ex2f(-x * LOG2E)); }
__device__ __forceinline__ float fsoftplus(float x) {
    float e = ex2f(-fabsf(x) * LOG2E);
    return fmaxf(x, 0.f) + LN2 * lg2f(1.f + e);
}

// ---------------------------------------------------------------------------
// Conversion kernels
// ---------------------------------------------------------------------------
__global__ __launch_bounds__(256)
void conv_A(const float* __restrict__ emb) {
    int idx = blockIdx.x * 256 + threadIdx.x;
    if (idx >= MPAD * HID) return;
    int e = idx >> 10;
    float a = (e < TS1) ? emb[idx] : 0.f;
    g_A[idx] = __float2half_rn(a);
}

__global__ __launch_bounds__(256)
void conv_B(const float* __restrict__ W) {
    int idx = blockIdx.x * 256 + threadIdx.x;
    if (idx >= NP * HID) return;
    int n = idx >> 10, k = idx & 1023;
    int c = n >> 10, h = n & 1023;
    float a = W[(size_t)(c_chunk[c] * HID + h) * WROW + k];
    g_B[idx] = __float2half_rn(a);
}

// ---------------------------------------------------------------------------
// GEMM half: 5-gate fp16 GEMM + activation epilogue -> g_table.
// Block 64e x 64h; warps arranged 2(m) x 4(n): warp tile 32m x 16n per gate.
// Per warp per ks: 2 A-ldsm + 5 B-ldsm -> 20 mma  (was 11 ldsm : 20 mma).
// ---------------------------------------------------------------------------
#define BK      32
#define KT      (KK / BK)                 // 32
#define TILE_B  (64 * 80)                 // 5120 B per 64-row tile per stage
#define STG_B   (6 * TILE_B)              // 30720 B per stage
#define SMEM_SZ (3 * STG_B)               // 92160 B

__global__ __launch_bounds__(256, 2)
void gemm_half(const float* __restrict__ brec, int bm_base) {
    extern __shared__ __align__(16) char smem[];
    const uint32_t sbase = smem_u32(smem);

    const int tid = threadIdx.x;
    const int wid = tid >> 5, lane = tid & 31;
    const int bh = blockIdx.x * 64;            // h-tile (within HID)
    const int bm = bm_base + blockIdx.y * 64;  // e-tile
    const int wm = (wid & 1) * 32;             // warp m offset: 0,32
    const int wn = (wid >> 1) * 16;            // warp n offset: 0,16,32,48

    const __half* gA = g_A + (size_t)bm * KK;
    const __half* gB = g_B + (size_t)bh * KK;

    const int lrow = tid >> 2, lch = tid & 3;

    auto issue = [&](int kt, int s) {
        const int k0 = kt * BK;
        const uint32_t st = sbase + s * STG_B;
        const uint32_t doff = lrow * 80 + lch * 16;
        const size_t   soff = (size_t)lrow * KK + k0 + lch * 8;
        CP_ASYNC16(st + doff, gA + soff);
#pragma unroll
        for (int g = 0; g < NG; g++)
            CP_ASYNC16(st + (g + 1) * TILE_B + doff,
                       gB + (size_t)g * HID * KK + soff);
    };

    // acc[g][mf*2+nf][4] : mf in {0,1} (m 0-15 / 16-31), nf in {0,1} (n 0-7 / 8-15)
    float acc[NG][4][4];
#pragma unroll
    for (int g = 0; g < NG; g++)
#pragma unroll
        for (int j = 0; j < 4; j++)
#pragma unroll
            for (int v = 0; v < 4; v++) acc[g][j][v] = 0.f;

    issue(0, 0); CP_COMMIT();
    issue(1, 1); CP_COMMIT();

    // shared ldmatrix lane offset pattern (rows lane&15, halves lane>>4)
    const uint32_t lmoff = (lane & 15) * 80 + (lane >> 4) * 16;

    int s = 0;
    for (int kt = 0; kt < KT; kt++) {
        if (kt < KT - 1) CP_WAIT1(); else CP_WAIT0();
        __syncthreads();

        const uint32_t aBase = sbase + s * STG_B;

#pragma unroll
        for (int ks = 0; ks < 2; ks++) {
            uint32_t af[2][4];
            ldsm_x4(af[0], aBase + (wm +  0) * 80 + ks * 32 + lmoff);
            ldsm_x4(af[1], aBase + (wm + 16) * 80 + ks * 32 + lmoff);
            if (ks == 0 && kt + 2 < KT) {
                int s2 = s + 2; if (s2 >= 3) s2 -= 3;
                issue(kt + 2, s2);
                CP_COMMIT();
            }
#pragma unroll
            for (int g = 0; g < NG; g++) {
                uint32_t bf[4];
                ldsm_x4(bf, aBase + (g + 1) * TILE_B + wn * 80 + ks * 32 + lmoff);
                // bf: {b0 n0-7, b0 n8-15, b1 n0-7, b1 n8-15}
                mma_f16(acc[g][0], af[0], bf[0], bf[2]);   // mf0 nf0
                mma_f16(acc[g][1], af[0], bf[1], bf[3]);   // mf0 nf1
                mma_f16(acc[g][2], af[1], bf[0], bf[2]);   // mf1 nf0
                mma_f16(acc[g][3], af[1], bf[1], bf[3]);   // mf1 nf1
            }
        }
        if (++s == 3) s = 0;
    }

    // ---- fused activation epilogue -> g_table ----
    const int cm = lane >> 2, cn = (lane & 3) * 2;

#pragma unroll
    for (int mf = 0; mf < 2; mf++) {
#pragma unroll
        for (int nf = 0; nf < 2; nf++) {
            const int j = mf * 2 + nf;
            const int col = bh + wn + nf * 8 + cn;
            const float2 bgi = *reinterpret_cast<const float2*>(brec + 0 * HID + col);
            const float2 bgz = *reinterpret_cast<const float2*>(brec + 2 * HID + col);
            const float2 bgo = *reinterpret_cast<const float2*>(brec + 3 * HID + col);
            const float2 bgb = *reinterpret_cast<const float2*>(brec + 4 * HID + col);
            const float2 bgd = *reinterpret_cast<const float2*>(brec + 6 * HID + col);
#pragma unroll
            for (int half = 0; half < 2; half++) {
                const int e = bm + wm + mf * 16 + cm + half * 8;
                if (e >= TS1) continue;
                const int v = half * 2;
                float gi0 = acc[0][j][v] + bgi.x, gi1 = acc[0][j][v + 1] + bgi.y;
                float gz0 = acc[1][j][v] + bgz.x, gz1 = acc[1][j][v + 1] + bgz.y;
                float go0 = acc[2][j][v] + bgo.x, go1 = acc[2][j][v + 1] + bgo.y;
                float gb0 = acc[3][j][v] + bgb.x, gb1 = acc[3][j][v + 1] + bgb.y;
                float gd0 = acc[4][j][v] + bgd.x, gd1 = acc[4][j][v + 1] + bgd.y;

                float tz0 = tanhf(gz0), tz1 = tanhf(gz1);
                float* T = g_table + (size_t)e * (4 * HID) + col;
                *reinterpret_cast<float2*>(T + 0 * HID) =
                    make_float2(fsigmoid(gi0) * tz0, fsigmoid(gi1) * tz1);
                *reinterpret_cast<float2*>(T + 1 * HID) =
                    make_float2(fsigmoid(gb0) * tz0, fsigmoid(gb1) * tz1);
                *reinterpret_cast<float2*>(T + 2 * HID) =
                    make_float2(fsigmoid(go0), fsigmoid(go1));
                *reinterpret_cast<float2*>(T + 3 * HID) =
                    make_float2(fsoftplus(gd0), fsoftplus(gd1));
            }
        }
    }
}

// ---------------------------------------------------------------------------
// Token kernel with e-range filter [elo, ehi). One block per token; blocks
// outside the range exit immediately (cheap). No bucketing needed.
// ---------------------------------------------------------------------------
__global__ __launch_bounds__(256)
void token_r(const int* __restrict__ ev, const float* __restrict__ dur,
             float* __restrict__ out, int elo, int ehi) {
    const int tok = blockIdx.x;        // = t*BATCH + b (matches output layout)
    const int t = tok >> 5;
    const int b = tok & 31;

    const int e = ev[b * SEQ + t];     // inputs are [B, T]
    if (e < elo || e >= ehi) return;
    const float d = dur[b * SEQ + t];
    const float dl = -d * LOG2E;       // exp(-gd*d) = ex2(gd * dl)

    const float* T = g_table + (size_t)e * (4 * HID);
    const int h = threadIdx.x * 4;

    float4 c  = *reinterpret_cast<const float4*>(T + 0 * HID + h);
    float4 cb = *reinterpret_cast<const float4*>(T + 1 * HID + h);
    float4 go = *reinterpret_cast<const float4*>(T + 2 * HID + h);
    float4 gd = *reinterpret_cast<const float4*>(T + 3 * HID + h);

    float4 hd;
    hd.x = go.x * tanhf(cb.x + (c.x - cb.x) * ex2f(gd.x * dl));
    hd.y = go.y * tanhf(cb.y + (c.y - cb.y) * ex2f(gd.y * dl));
    hd.z = go.z * tanhf(cb.z + (c.z - cb.z) * ex2f(gd.z * dl));
    hd.w = go.w * tanhf(cb.w + (c.w - cb.w) * ex2f(gd.w * dl));

    const size_t stride = (size_t)SEQ * BATCH * HID;
    float* base = out + (size_t)tok * HID + h;

    __stcs(reinterpret_cast<float4*>(base + 0 * stride), hd);
    __stcs(reinterpret_cast<float4*>(base + 1 * stride), c);
    __stcs(reinterpret_cast<float4*>(base + 2 * stride), cb);
    __stcs(reinterpret_cast<float4*>(base + 3 * stride), go);
    __stcs(reinterpret_cast<float4*>(base + 4 * stride), gd);
}

// ---------------------------------------------------------------------------
extern "C" void kernel_launch(void* const* d_in, const int* in_sizes, int n_in,
                              void* d_out, int out_size) {
    const int*   ev  = (const int*)  d_in[0];   // event_seqs   [32, 512] int32
    const float* dur = (const float*)d_in[1];   // duration_seqs[32, 512]
    const float* emb = (const float*)d_in[2];   // emb_table [1001, 1024]
    const float* W   = (const float*)d_in[3];   // W_rec [7168, 2048]
    const float* br  = (const float*)d_in[4];   // b_rec [7168]
    float* out = (float*)d_out;                 // [5, 512, 32, 1024]

    static cudaStream_t s1, s2;
    static cudaEvent_t evFork, evG0, evG1, evJ1, evJ2;
    static bool init_done = false;
    if (!init_done) {
        cudaFuncSetAttribute(gemm_half,
                             cudaFuncAttributeMaxDynamicSharedMemorySize,
                             SMEM_SZ);
        cudaStreamCreateWithFlags(&s1, cudaStreamNonBlocking);
        cudaStreamCreateWithFlags(&s2, cudaStreamNonBlocking);
        cudaEventCreateWithFlags(&evFork, cudaEventDisableTiming);
        cudaEventCreateWithFlags(&evG0,   cudaEventDisableTiming);
        cudaEventCreateWithFlags(&evG1,   cudaEventDisableTiming);
        cudaEventCreateWithFlags(&evJ1,   cudaEventDisableTiming);
        cudaEventCreateWithFlags(&evJ2,   cudaEventDisableTiming);
        init_done = true;
    }

    // ---- fork ----
    cudaEventRecord(evFork, 0);
    cudaStreamWaitEvent(s1, evFork, 0);
    cudaStreamWaitEvent(s2, evFork, 0);

    // ---- s1: conversions + gemm halves ----
    conv_A<<<(MPAD * HID + 255) / 256, 256, 0, s1>>>(emb);
    conv_B<<<(NP * HID + 255) / 256, 256, 0, s1>>>(W);
    dim3 gh(HID / 64, ESPLIT / 64);             // (16, 8) = 128 blocks
    gemm_half<<<gh, 256, SMEM_SZ, s1>>>(br, 0);       // e 0..511
    cudaEventRecord(evG0, s1);
    gemm_half<<<gh, 256, SMEM_SZ, s1>>>(br, ESPLIT);  // e 512..1023
    cudaEventRecord(evG1, s1);

    // ---- s2: token halves (lo overlaps gemm half 1 if scheduler allows) ----
    cudaStreamWaitEvent(s2, evG0, 0);
    token_r<<<NTOK, 256, 0, s2>>>(ev, dur, out, 0, ESPLIT);
    cudaStreamWaitEvent(s2, evG1, 0);
    token_r<<<NTOK, 256, 0, s2>>>(ev, dur, out, ESPLIT, TS1);

    // ---- join ----
    cudaEventRecord(evJ1, s1);
    cudaEventRecord(evJ2, s2);
    cudaStreamWaitEvent(0, evJ1, 0);
    cudaStreamWaitEvent(0, evJ2, 0);
}

// round 11
// speedup vs baseline: 1.2768x; 1.0342x over previous
#include <cuda_runtime.h>
#include <cuda_fp16.h>
#include <cstdint>

#define HID   1024
#define TS1   1001            // TYPE_SIZE + 1 embedding rows
#define MPAD  1024            // padded M (16 tiles of 64)
#define BATCH 32
#define SEQ   512
#define NTOK  (BATCH * SEQ)
#define NG    5               // used gates: gi, gz, go, gib, gd
#define NP    (NG * HID)      // 5120
#define WROW  2048            // W_rec row stride (2H)
#define KK    1024            // K (single-pass fp16)

// ---------------- device-global scratch (no allocs allowed) ----------------
__device__ __half g_A[MPAD * KK];            // 2 MB
__device__ __half g_B[NP * KK];              // 10 MB
__device__ float g_table[TS1 * 4 * HID];     // 16.4 MB {c, c_bar, sig(go), sp(gd)}

__constant__ int c_chunk[NG] = {0, 2, 3, 4, 6};   // gi, gz, go, gib, gd

// ---------------- base-target PTX helpers ----------------
__device__ __forceinline__ uint32_t smem_u32(const void* p) {
    uint32_t a;
    asm("{ .reg .u64 t; cvta.to.shared.u64 t, %1; cvt.u32.u64 %0, t; }"
        : "=r"(a) : "l"(p));
    return a;
}
#define CP_ASYNC16(dst, src) \
    asm volatile("cp.async.cg.shared.global [%0], [%1], 16;" \
                 :: "r"(dst), "l"(src))
#define CP_COMMIT() asm volatile("cp.async.commit_group;" ::: "memory")
#define CP_WAIT0()  asm volatile("cp.async.wait_group 0;" ::: "memory")
#define CP_WAIT1()  asm volatile("cp.async.wait_group 1;" ::: "memory")

__device__ __forceinline__ void ldsm_x4(uint32_t* r, uint32_t addr) {
    asm volatile("ldmatrix.sync.aligned.m8n8.x4.shared.b16 {%0,%1,%2,%3}, [%4];"
        : "=r"(r[0]), "=r"(r[1]), "=r"(r[2]), "=r"(r[3]) : "r"(addr));
}
__device__ __forceinline__ void mma_f16(float* c, const uint32_t* a,
                                        uint32_t b0, uint32_t b1) {
    asm volatile(
        "mma.sync.aligned.m16n8k16.row.col.f32.f16.f16.f32 "
        "{%0,%1,%2,%3}, {%4,%5,%6,%7}, {%8,%9}, {%0,%1,%2,%3};"
        : "+f"(c[0]), "+f"(c[1]), "+f"(c[2]), "+f"(c[3])
        : "r"(a[0]), "r"(a[1]), "r"(a[2]), "r"(a[3]), "r"(b0), "r"(b1));
}

// ---- fast transcendentals (MUFU) ----
#define LOG2E 1.4426950408889634f
#define LN2   0.6931471805599453f
__device__ __forceinline__ float ex2f(float x) {
    float y; asm("ex2.approx.f32 %0, %1;" : "=f"(y) : "f"(x)); return y;
}
__device__ __forceinline__ float lg2f(float x) {
    float y; asm("lg2.approx.f32 %0, %1;" : "=f"(y) : "f"(x)); return y;
}
__device__ __forceinline__ float rcpf(float x) {
    float y; asm("rcp.approx.f32 %0, %1;" : "=f"(y) : "f"(x)); return y;
}
__device__ __forceinline__ float fsigmoid(float x){ return rcpf(1.f + ex2f(-x * LOG2E)); }
__device__ __forceinline__ float fsoftplus(float x) {
    float e = ex2f(-fabsf(x) * LOG2E);
    return fmaxf(x, 0.f) + LN2 * lg2f(1.f + e);
}

// ---------------------------------------------------------------------------
// Conversion kernels
// ---------------------------------------------------------------------------
__global__ __launch_bounds__(256)
void conv_A(const float* __restrict__ emb) {
    int idx = blockIdx.x * 256 + threadIdx.x;
    if (idx >= MPAD * HID) return;
    int e = idx >> 10;
    float a = (e < TS1) ? emb[idx] : 0.f;
    g_A[idx] = __float2half_rn(a);
}

__global__ __launch_bounds__(256)
void conv_B(const float* __restrict__ W) {
    int idx = blockIdx.x * 256 + threadIdx.x;
    if (idx >= NP * HID) return;
    int n = idx >> 10, k = idx & 1023;
    int c = n >> 10, h = n & 1023;
    float a = W[(size_t)(c_chunk[c] * HID + h) * WROW + k];
    g_B[idx] = __float2half_rn(a);
}

// ---------------------------------------------------------------------------
// GEMM (full): 5-gate fp16 GEMM + activation epilogue -> g_table.
// Grid (16,16) = 256 blocks -> 2 CTAs/SM (16 warps/SM).
// Block 64e x 64h; warps 2(m) x 4(n): per warp per ks: 2 A + 5 B ldsm, 20 mma.
// ---------------------------------------------------------------------------
#define BK      32
#define KT      (KK / BK)                 // 32
#define TILE_B  (64 * 80)                 // 5120 B per 64-row tile per stage
#define STG_B   (6 * TILE_B)              // 30720 B per stage
#define SMEM_SZ (3 * STG_B)               // 92160 B  (x2 CTAs = 184320 <= 228KB)

__global__ __launch_bounds__(256, 2)
void gemm_full(const float* __restrict__ brec) {
    extern __shared__ __align__(16) char smem[];
    const uint32_t sbase = smem_u32(smem);

    const int tid = threadIdx.x;
    const int wid = tid >> 5, lane = tid & 31;
    const int bh = blockIdx.x * 64;            // h-tile (within HID)
    const int bm = blockIdx.y * 64;            // e-tile
    const int wm = (wid & 1) * 32;             // warp m offset: 0,32
    const int wn = (wid >> 1) * 16;            // warp n offset: 0,16,32,48

    const __half* gA = g_A + (size_t)bm * KK;
    const __half* gB = g_B + (size_t)bh * KK;

    const int lrow = tid >> 2, lch = tid & 3;

    auto issue = [&](int kt, int s) {
        const int k0 = kt * BK;
        const uint32_t st = sbase + s * STG_B;
        const uint32_t doff = lrow * 80 + lch * 16;
        const size_t   soff = (size_t)lrow * KK + k0 + lch * 8;
        CP_ASYNC16(st + doff, gA + soff);
#pragma unroll
        for (int g = 0; g < NG; g++)
            CP_ASYNC16(st + (g + 1) * TILE_B + doff,
                       gB + (size_t)g * HID * KK + soff);
    };

    // acc[g][mf*2+nf][4] : mf in {0,1} (m 0-15/16-31), nf in {0,1} (n 0-7/8-15)
    float acc[NG][4][4];
#pragma unroll
    for (int g = 0; g < NG; g++)
#pragma unroll
        for (int j = 0; j < 4; j++)
#pragma unroll
            for (int v = 0; v < 4; v++) acc[g][j][v] = 0.f;

    issue(0, 0); CP_COMMIT();
    issue(1, 1); CP_COMMIT();

    const uint32_t lmoff = (lane & 15) * 80 + (lane >> 4) * 16;

    int s = 0;
    for (int kt = 0; kt < KT; kt++) {
        if (kt < KT - 1) CP_WAIT1(); else CP_WAIT0();
        __syncthreads();

        const uint32_t aBase = sbase + s * STG_B;

#pragma unroll
        for (int ks = 0; ks < 2; ks++) {
            uint32_t af[2][4];
            ldsm_x4(af[0], aBase + (wm +  0) * 80 + ks * 32 + lmoff);
            ldsm_x4(af[1], aBase + (wm + 16) * 80 + ks * 32 + lmoff);
            if (ks == 0 && kt + 2 < KT) {
                int s2 = s + 2; if (s2 >= 3) s2 -= 3;
                issue(kt + 2, s2);
                CP_COMMIT();
            }
#pragma unroll
            for (int g = 0; g < NG; g++) {
                uint32_t bf[4];
                ldsm_x4(bf, aBase + (g + 1) * TILE_B + wn * 80 + ks * 32 + lmoff);
                mma_f16(acc[g][0], af[0], bf[0], bf[2]);   // mf0 nf0
                mma_f16(acc[g][1], af[0], bf[1], bf[3]);   // mf0 nf1
                mma_f16(acc[g][2], af[1], bf[0], bf[2]);   // mf1 nf0
                mma_f16(acc[g][3], af[1], bf[1], bf[3]);   // mf1 nf1
            }
        }
        if (++s == 3) s = 0;
    }

    // ---- fused activation epilogue -> g_table ----
    const int cm = lane >> 2, cn = (lane & 3) * 2;

#pragma unroll
    for (int mf = 0; mf < 2; mf++) {
#pragma unroll
        for (int nf = 0; nf < 2; nf++) {
            const int j = mf * 2 + nf;
            const int col = bh + wn + nf * 8 + cn;
            const float2 bgi = *reinterpret_cast<const float2*>(brec + 0 * HID + col);
            const float2 bgz = *reinterpret_cast<const float2*>(brec + 2 * HID + col);
            const float2 bgo = *reinterpret_cast<const float2*>(brec + 3 * HID + col);
            const float2 bgb = *reinterpret_cast<const float2*>(brec + 4 * HID + col);
            const float2 bgd = *reinterpret_cast<const float2*>(brec + 6 * HID + col);
#pragma unroll
            for (int half = 0; half < 2; half++) {
                const int e = bm + wm + mf * 16 + cm + half * 8;
                if (e >= TS1) continue;
                const int v = half * 2;
                float gi0 = acc[0][j][v] + bgi.x, gi1 = acc[0][j][v + 1] + bgi.y;
                float gz0 = acc[1][j][v] + bgz.x, gz1 = acc[1][j][v + 1] + bgz.y;
                float go0 = acc[2][j][v] + bgo.x, go1 = acc[2][j][v + 1] + bgo.y;
                float gb0 = acc[3][j][v] + bgb.x, gb1 = acc[3][j][v + 1] + bgb.y;
                float gd0 = acc[4][j][v] + bgd.x, gd1 = acc[4][j][v + 1] + bgd.y;

                float tz0 = tanhf(gz0), tz1 = tanhf(gz1);
                float* T = g_table + (size_t)e * (4 * HID) + col;
                *reinterpret_cast<float2*>(T + 0 * HID) =
                    make_float2(fsigmoid(gi0) * tz0, fsigmoid(gi1) * tz1);
                *reinterpret_cast<float2*>(T + 1 * HID) =
                    make_float2(fsigmoid(gb0) * tz0, fsigmoid(gb1) * tz1);
                *reinterpret_cast<float2*>(T + 2 * HID) =
                    make_float2(fsigmoid(go0), fsigmoid(go1));
                *reinterpret_cast<float2*>(T + 3 * HID) =
                    make_float2(fsoftplus(gd0), fsoftplus(gd1));
            }
        }
    }
}

// ---------------------------------------------------------------------------
// Token kernel: per-token gather + decay + write 5 outputs [5, T, B, H]
// ---------------------------------------------------------------------------
__global__ __launch_bounds__(256)
void token_kernel(const int* __restrict__ ev, const float* __restrict__ dur,
                  float* __restrict__ out) {
    const int tok = blockIdx.x;        // = t*BATCH + b (matches output layout)
    const int t = tok >> 5;
    const int b = tok & 31;

    const int   e = ev[b * SEQ + t];   // inputs are [B, T]
    const float d = dur[b * SEQ + t];
    const float dl = -d * LOG2E;       // exp(-gd*d) = ex2(gd * dl)

    const float* T = g_table + (size_t)e * (4 * HID);
    const int h = threadIdx.x * 4;

    float4 c  = *reinterpret_cast<const float4*>(T + 0 * HID + h);
    float4 cb = *reinterpret_cast<const float4*>(T + 1 * HID + h);
    float4 go = *reinterpret_cast<const float4*>(T + 2 * HID + h);
    float4 gd = *reinterpret_cast<const float4*>(T + 3 * HID + h);

    float4 hd;
    hd.x = go.x * tanhf(cb.x + (c.x - cb.x) * ex2f(gd.x * dl));
    hd.y = go.y * tanhf(cb.y + (c.y - cb.y) * ex2f(gd.y * dl));
    hd.z = go.z * tanhf(cb.z + (c.z - cb.z) * ex2f(gd.z * dl));
    hd.w = go.w * tanhf(cb.w + (c.w - cb.w) * ex2f(gd.w * dl));

    const size_t stride = (size_t)SEQ * BATCH * HID;
    float* base = out + (size_t)tok * HID + h;

    __stcs(reinterpret_cast<float4*>(base + 0 * stride), hd);
    __stcs(reinterpret_cast<float4*>(base + 1 * stride), c);
    __stcs(reinterpret_cast<float4*>(base + 2 * stride), cb);
    __stcs(reinterpret_cast<float4*>(base + 3 * stride), go);
    __stcs(reinterpret_cast<float4*>(base + 4 * stride), gd);
}

// ---------------------------------------------------------------------------
extern "C" void kernel_launch(void* const* d_in, const int* in_sizes, int n_in,
                              void* d_out, int out_size) {
    const int*   ev  = (const int*)  d_in[0];   // event_seqs   [32, 512] int32
    const float* dur = (const float*)d_in[1];   // duration_seqs[32, 512]
    const float* emb = (const float*)d_in[2];   // emb_table [1001, 1024]
    const float* W   = (const float*)d_in[3];   // W_rec [7168, 2048]
    const float* br  = (const float*)d_in[4];   // b_rec [7168]
    float* out = (float*)d_out;                 // [5, 512, 32, 1024]

    static bool init_done = false;
    if (!init_done) {
        cudaFuncSetAttribute(gemm_full,
                             cudaFuncAttributeMaxDynamicSharedMemorySize,
                             SMEM_SZ);
        init_done = true;
    }

    conv_A<<<(MPAD * HID + 255) / 256, 256>>>(emb);
    conv_B<<<(NP * HID + 255) / 256, 256>>>(W);

    dim3 g1(HID / 64, MPAD / 64);               // (16, 16) = 256 blocks
    gemm_full<<<g1, 256, SMEM_SZ>>>(br);

    token_kernel<<<NTOK, 256>>>(ev, dur, out);
}